// round 15
// baseline (speedup 1.0000x reference)
#include <cuda_runtime.h>

#define B_   2
#define S_   2048
#define D_   1024
#define H_   16
#define HD_  64
#define MEM_ 512
#define SK_  2560
#define BH_  32
#define NROW (BH_*S_)   // 65536
#define LCAP 36         // per-lane candidate slots
#define CAP_ (32*LCAP)  // 1152 per warp

// Scratch (static device allocs only)
__device__ float  g_q[BH_*S_*HD_];
__device__ float  g_k[BH_*SK_*HD_];
__device__ float  g_v[BH_*SK_*HD_];
__device__ float  g_ctx[B_*S_*D_];
__device__ float  g_scores[(size_t)NROW*SK_];   // 671 MB
__device__ float4 g_stats[NROW];                // thr, max, -, -

__device__ __forceinline__ unsigned f2tf(float f){
    unsigned r; asm("cvt.rna.tf32.f32 %0, %1;" : "=r"(r) : "f"(f)); return r;
}
__device__ __forceinline__ void tfsplit(float x, unsigned& h, unsigned& l){
    h = f2tf(x);
    l = f2tf(x - __uint_as_float(h));
}
__device__ __forceinline__ void mma8(float* c, const unsigned* a, const unsigned* b){
    asm volatile("mma.sync.aligned.m16n8k8.row.col.f32.tf32.tf32.f32 "
      "{%0,%1,%2,%3}, {%4,%5,%6,%7}, {%8,%9}, {%0,%1,%2,%3};\n"
      : "+f"(c[0]), "+f"(c[1]), "+f"(c[2]), "+f"(c[3])
      : "r"(a[0]),"r"(a[1]),"r"(a[2]),"r"(a[3]), "r"(b[0]),"r"(b[1]));
}
__device__ __forceinline__ void mma8x3(float* c, const unsigned* ah, const unsigned* al,
                                       const unsigned* bh, const unsigned* bl){
    mma8(c, al, bh);
    mma8(c, ah, bl);
    mma8(c, ah, bh);
}

// ---------------------------------------------------------------------------
// Dense GEMM (3xTF32). mode 3: row-major dst (out proj, A=g_ctx);
// mode 4: fused QKV — gridDim.z=3 selects (Wq,bq)->Q, (Wk,bk)->K, (Wv,bv)->V.
// ---------------------------------------------------------------------------
__global__ __launch_bounds__(256, 2) void gemm4k(
    const float* __restrict__ A,
    const float* __restrict__ W,  const float* __restrict__ bias,
    const float* __restrict__ W2, const float* __restrict__ bias2,
    const float* __restrict__ W3, const float* __restrict__ bias3,
    float* __restrict__ dst, int mode)
{
    __shared__ unsigned Ah[2][128*20], Al[2][128*20];
    __shared__ unsigned Bh[2][16*136], Bl[2][16*136];
    int em = mode;
    const float* Wp = W;
    const float* bp = bias;
    if (mode == 4) {
        em = blockIdx.z;                   // 0=Q, 1=K, 2=V
        if (em == 1) { Wp = W2; bp = bias2; }
        else if (em == 2) { Wp = W3; bp = bias3; }
    }
    const float* Ap = (em==3) ? g_ctx : A;
    const int t = threadIdx.x;
    const int m0 = blockIdx.y*128, n0 = blockIdx.x*128;
    const int w = t>>5, lane = t&31, g = lane>>2, tig = lane&3;
    const int wm = w>>2, wn = w&3;

    const int am_r = t>>2;
    const int am_k = (t&3)*4;
    const int bm_k = t>>5;
    const int bm_n = (t&31)*4;

    const float* Arow0 = Ap + (size_t)(m0+am_r)*1024 + am_k;
    const float* Arow1 = Arow0 + (size_t)64*1024;
    const float* Wrow0 = Wp + (size_t)bm_k*1024 + n0 + bm_n;
    const float* Wrow1 = Wrow0 + (size_t)8*1024;

    float acc[4][4][4];
    #pragma unroll
    for(int i=0;i<4;i++)
        #pragma unroll
        for(int j=0;j<4;j++)
            #pragma unroll
            for(int c=0;c<4;c++) acc[i][j][c]=0.f;

    float4 la0,la1,lb0,lb1;
    auto ldg = [&](int kt){
        la0 = *(const float4*)(Arow0 + kt*16);
        la1 = *(const float4*)(Arow1 + kt*16);
        lb0 = *(const float4*)(Wrow0 + (size_t)kt*16*1024);
        lb1 = *(const float4*)(Wrow1 + (size_t)kt*16*1024);
    };
    auto sts = [&](int buf){
        uint4 uh, ul;
        tfsplit(la0.x,uh.x,ul.x); tfsplit(la0.y,uh.y,ul.y);
        tfsplit(la0.z,uh.z,ul.z); tfsplit(la0.w,uh.w,ul.w);
        *(uint4*)&Ah[buf][am_r*20 + am_k] = uh;
        *(uint4*)&Al[buf][am_r*20 + am_k] = ul;
        tfsplit(la1.x,uh.x,ul.x); tfsplit(la1.y,uh.y,ul.y);
        tfsplit(la1.z,uh.z,ul.z); tfsplit(la1.w,uh.w,ul.w);
        *(uint4*)&Ah[buf][(am_r+64)*20 + am_k] = uh;
        *(uint4*)&Al[buf][(am_r+64)*20 + am_k] = ul;
        tfsplit(lb0.x,uh.x,ul.x); tfsplit(lb0.y,uh.y,ul.y);
        tfsplit(lb0.z,uh.z,ul.z); tfsplit(lb0.w,uh.w,ul.w);
        *(uint4*)&Bh[buf][bm_k*136 + bm_n] = uh;
        *(uint4*)&Bl[buf][bm_k*136 + bm_n] = ul;
        tfsplit(lb1.x,uh.x,ul.x); tfsplit(lb1.y,uh.y,ul.y);
        tfsplit(lb1.z,uh.z,ul.z); tfsplit(lb1.w,uh.w,ul.w);
        *(uint4*)&Bh[buf][(bm_k+8)*136 + bm_n] = uh;
        *(uint4*)&Bl[buf][(bm_k+8)*136 + bm_n] = ul;
    };
    auto compute = [&](int buf){
        #pragma unroll
        for(int kk=0;kk<2;kk++){
            unsigned ah[4][4], al[4][4], bh[4][2], bl[4][2];
            #pragma unroll
            for(int mi=0;mi<4;mi++){
                int base = (wm*64+mi*16+g)*20 + kk*8 + tig;
                ah[mi][0]=Ah[buf][base];       al[mi][0]=Al[buf][base];
                ah[mi][1]=Ah[buf][base+8*20];  al[mi][1]=Al[buf][base+8*20];
                ah[mi][2]=Ah[buf][base+4];     al[mi][2]=Al[buf][base+4];
                ah[mi][3]=Ah[buf][base+8*20+4];al[mi][3]=Al[buf][base+8*20+4];
            }
            #pragma unroll
            for(int nj=0;nj<4;nj++){
                int base = (kk*8+tig)*136 + wn*32+nj*8+g;
                bh[nj][0]=Bh[buf][base];        bl[nj][0]=Bl[buf][base];
                bh[nj][1]=Bh[buf][base+4*136];  bl[nj][1]=Bl[buf][base+4*136];
            }
            #pragma unroll
            for(int mi=0;mi<4;mi++)
                #pragma unroll
                for(int nj=0;nj<4;nj++)
                    mma8x3(acc[mi][nj], ah[mi], al[mi], bh[nj], bl[nj]);
        }
    };

    ldg(0); sts(0); __syncthreads();
    for(int kt=0;kt<64;kt++){
        if(kt<63) ldg(kt+1);
        compute(kt&1);
        if(kt<63){ sts((kt+1)&1); __syncthreads(); }
    }

    const int b = m0>>11;
    #pragma unroll
    for(int nj=0;nj<4;nj++){
        int c0 = n0 + wn*32 + nj*8 + 2*tig;
        float bv0 = bp[c0], bv1 = bp[c0+1];
        int h = c0>>6, hd = c0&63;
        #pragma unroll
        for(int mi=0;mi<4;mi++){
            int r0 = m0 + wm*64 + mi*16 + g;
            int s0 = r0 & 2047;
            float2 v0 = {acc[mi][nj][0]+bv0, acc[mi][nj][1]+bv1};
            float2 v1 = {acc[mi][nj][2]+bv0, acc[mi][nj][3]+bv1};
            if(em==3){
                *(float2*)(dst + (size_t)r0*1024 + c0)     = v0;
                *(float2*)(dst + (size_t)(r0+8)*1024 + c0) = v1;
            } else {
                float* base = (em==0)? g_q : (em==1? g_k : g_v);
                size_t roff = (em==0)? ((size_t)(b*16+h)*S_)
                                     : ((size_t)(b*16+h)*SK_ + MEM_);
                *(float2*)(base + (roff + s0)*64 + hd)     = v0;
                *(float2*)(base + (roff + s0 + 8)*64 + hd) = v1;
            }
        }
    }
}

__global__ void copy_past_kernel(const float* __restrict__ pk,
                                 const float* __restrict__ pv)
{
    int i = blockIdx.x * blockDim.x + threadIdx.x;
    if (i < BH_ * MEM_ * HD_ / 4) {
        int e = i * 4;
        int bh = e >> 15, rem = e & 32767;
        *(float4*)(g_k + (size_t)bh*(SK_*HD_) + rem) = *(const float4*)(pk + e);
        *(float4*)(g_v + (size_t)bh*(SK_*HD_) + rem) = *(const float4*)(pv + e);
    }
}
__global__ void copy_new_kernel(float* __restrict__ nk, float* __restrict__ nv)
{
    int i = blockIdx.x * blockDim.x + threadIdx.x;
    if (i < BH_ * MEM_ * HD_ / 4) {
        int e = i * 4;
        int bh = e >> 15, rem = e & 32767;
        size_t src = (size_t)bh*(SK_*HD_) + S_*HD_ + rem;
        *(float4*)(nk + e) = *(const float4*)(g_k + src);
        *(float4*)(nv + e) = *(const float4*)(g_v + src);
    }
}

// ---------------------------------------------------------------------------
// scores = (Q*0.125) K^T -> g_scores. Single-pass tf32, scale folded into Q.
// ---------------------------------------------------------------------------
__global__ __launch_bounds__(256, 2) void scores_k()
{
    extern __shared__ unsigned shsc[];
    unsigned* Qs = shsc;               // [128][68] tf32 bits (pre-scaled)
    unsigned* Ks = shsc + 128*68;      // [128][68]
    const int z = blockIdx.z;
    const int m0 = blockIdx.y*128, n0 = blockIdx.x*128;
    const int t = threadIdx.x, w = t>>5, lane=t&31, g=lane>>2, tig=lane&3;
    const int wm = w>>2, wn = w&3;
    const float* Q = g_q + ((size_t)z*S_ + m0)*64;
    const float* K = g_k + ((size_t)z*SK_ + n0)*64;

    #pragma unroll
    for(int i=0;i<8;i++){
        int idx = t + i*256, r = idx>>4, c = (idx&15)*4;
        float4 a = *(const float4*)(Q + (size_t)r*64 + c);
        uint4 ua = {f2tf(a.x*0.125f),f2tf(a.y*0.125f),
                    f2tf(a.z*0.125f),f2tf(a.w*0.125f)};
        *(uint4*)&Qs[r*68+c] = ua;
        float4 bb = *(const float4*)(K + (size_t)r*64 + c);
        uint4 ub = {f2tf(bb.x),f2tf(bb.y),f2tf(bb.z),f2tf(bb.w)};
        *(uint4*)&Ks[r*68+c] = ub;
    }
    __syncthreads();

    float acc[4][4][4] = {};
    #pragma unroll
    for(int kk=0;kk<8;kk++){
        unsigned af[4][4], bf[4][2];
        #pragma unroll
        for(int mi=0;mi<4;mi++){
            const unsigned* p = &Qs[(wm*64+mi*16+g)*68 + kk*8 + tig];
            af[mi][0]=p[0]; af[mi][1]=p[8*68]; af[mi][2]=p[4]; af[mi][3]=p[8*68+4];
        }
        #pragma unroll
        for(int nj=0;nj<4;nj++){
            const unsigned* p = &Ks[(wn*32+nj*8+g)*68 + kk*8 + tig];
            bf[nj][0]=p[0]; bf[nj][1]=p[4];
        }
        #pragma unroll
        for(int mi=0;mi<4;mi++)
            #pragma unroll
            for(int nj=0;nj<4;nj++) mma8(acc[mi][nj], af[mi], bf[nj]);
    }

    float* out = g_scores + ((size_t)(z*S_ + m0))*SK_ + n0;
    #pragma unroll
    for(int mi=0;mi<4;mi++){
        int r0 = wm*64+mi*16+g;
        #pragma unroll
        for(int nj=0;nj<4;nj++){
            int c0 = wn*32+nj*8+2*tig;
            float2 v0 = {acc[mi][nj][0], acc[mi][nj][1]};
            float2 v1 = {acc[mi][nj][2], acc[mi][nj][3]};
            *(float2*)(out + (size_t)r0*SK_ + c0)     = v0;
            *(float2*)(out + (size_t)(r0+8)*SK_ + c0) = v1;
        }
    }
}

// ---------------------------------------------------------------------------
// Radix helpers
// ---------------------------------------------------------------------------
__device__ __forceinline__ unsigned f2key(float f) {
    unsigned u = __float_as_uint(f);
    return u ^ (unsigned(int(u) >> 31) | 0x80000000u);   // SHF + LOP3
}
__device__ __forceinline__ float key2f(unsigned k) {
    unsigned u = (k & 0x80000000u) ? (k ^ 0x80000000u) : ~k;
    return __uint_as_float(u);
}
__device__ __forceinline__ int resolve256(const unsigned* hist, int lane, int& k){
    unsigned cnt[8], local = 0;
    #pragma unroll
    for (int j = 0; j < 8; j++) { cnt[j] = hist[lane*8+j]; local += cnt[j]; }
    unsigned x = local;
    #pragma unroll
    for (int off = 1; off < 32; off <<= 1) {
        unsigned y = __shfl_up_sync(0xffffffffu, x, off);
        if (lane >= off) x += y;
    }
    unsigned incl = x, excl = x - local;
    bool flag = ((unsigned)k >= excl) && ((unsigned)k < incl);
    unsigned bal = __ballot_sync(0xffffffffu, flag);
    int src = __ffs(bal) - 1;
    int digit = 0, newk = 0;
    if (lane == src) {
        unsigned c = excl; int j = 0;
        for (; j < 8; j++) { if (c + cnt[j] > (unsigned)k) break; c += cnt[j]; }
        digit = lane*8 + j;
        newk  = k - (int)c;
    }
    digit = __shfl_sync(0xffffffffu, digit, src);
    k     = __shfl_sync(0xffffffffu, newk,  src);
    return digit;
}

// ---------------------------------------------------------------------------
// thresh_k v5: warp per row; emits (thr, masked max). Moment bracket +
// LANE-PRIVATE candidate gather (no ballots/atomics in the stream).
// Fallback (bracket miss / lane overflow / huge mask effect) = full radix.
// ---------------------------------------------------------------------------
__global__ __launch_bounds__(256) void thresh_k(const int* __restrict__ amask)
{
    extern __shared__ unsigned tsm[];
    unsigned* cand = tsm;                        // 8*CAP_
    unsigned* hist = cand + 8*CAP_;              // 8*264
    unsigned* mbits= hist + 8*264;               // 64 words
    __shared__ int s_allones;
    const int t = threadIdx.x, w = t>>5, lane = t&31;
    const int row_id = blockIdx.x*8 + w;
    const int bh = row_id >> 11;
    const int b = bh >> 4;
    const float* src = g_scores + (size_t)row_id*SK_;
    const int* am = amask + b*S_;
    unsigned* cw = cand + w*CAP_;
    unsigned* hw = hist + w*264;
    unsigned* lseg = cw + lane*LCAP;             // lane-private slots

    if (t == 0) s_allones = 1;
    __syncthreads();
    if (t < 64) {
        unsigned wb = 0;
        for (int j = 0; j < 32; j++) wb |= (am[t*32+j] != 0 ? (1u<<j) : 0u);
        mbits[t] = wb;
        if (wb != 0xFFFFFFFFu) s_allones = 0;
    }
    __syncthreads();
    const bool allones = (s_allones != 0);
    auto masked = [&](int kg)->bool {
        if (kg < MEM_) return true;
        int s = kg - MEM_;
        return (mbits[s>>5] >> (s&31)) & 1u;
    };

    // ---- Pass 1: moments + masked max ------------------------------------
    float s1 = 0.f, s2 = 0.f, m = -1e30f;
    if (allones) {
        for(int it=0; it<10; it++){
            float4 va = *(const float4*)(src + (it*64 + lane)*4);
            float4 vb = *(const float4*)(src + (it*64 + 32 + lane)*4);
            #pragma unroll
            for(int j=0;j<4;j++){
                float x = (&va.x)[j]; s1 += x; s2 += x*x; m = fmaxf(m, x);
            }
            #pragma unroll
            for(int j=0;j<4;j++){
                float x = (&vb.x)[j]; s1 += x; s2 += x*x; m = fmaxf(m, x);
            }
        }
    } else {
        for(int it=0; it<10; it++){
            int ia = (it*64 + lane)*4;
            int ib = (it*64 + 32 + lane)*4;
            float4 va = *(const float4*)(src + ia);
            float4 vb = *(const float4*)(src + ib);
            #pragma unroll
            for(int j=0;j<4;j++){
                float x = (&va.x)[j]; s1 += x; s2 += x*x;
                if (masked(ia+j)) m = fmaxf(m, x);
            }
            #pragma unroll
            for(int j=0;j<4;j++){
                float x = (&vb.x)[j]; s1 += x; s2 += x*x;
                if (masked(ib+j)) m = fmaxf(m, x);
            }
        }
    }
    #pragma unroll
    for(int off=16;off;off>>=1){
        s1 += __shfl_xor_sync(0xffffffffu,s1,off);
        s2 += __shfl_xor_sync(0xffffffffu,s2,off);
        m = fmaxf(m, __shfl_xor_sync(0xffffffffu,m,off));
    }
    const float inv_n = 1.0f/2560.f;
    float mu  = s1*inv_n;
    float var = fmaxf(s2*inv_n - mu*mu, 0.f);
    float sg  = sqrtf(var);
    float lo  = mu - 2.1f*sg;    // bracket rank-256 (z~-1.28)
    float hi  = mu - 0.6f*sg;

    // ---- Pass 2: count<lo + lane-private gather of [lo,hi) ---------------
    int clo = 0, cnt = 0;
    for(int it=0; it<10; it++){
        float4 va = *(const float4*)(src + (it*64 + lane)*4);
        float4 vb = *(const float4*)(src + (it*64 + 32 + lane)*4);
        #pragma unroll
        for(int half=0; half<2; half++){
            const float4& v = half ? vb : va;
            #pragma unroll
            for(int j=0;j<4;j++){
                float x = (&v.x)[j];
                bool blo = x < lo;
                bool bin = (!blo) & (x < hi);
                clo += blo;
                if (bin){
                    if (cnt < LCAP) lseg[cnt] = f2key(x);
                    cnt++;
                }
            }
        }
    }
    bool ovf = __any_sync(0xffffffffu, cnt > LCAP);
    int ctot = cnt, csum = clo;
    #pragma unroll
    for(int off=16;off;off>>=1){
        ctot += __shfl_xor_sync(0xffffffffu,ctot,off);
        csum += __shfl_xor_sync(0xffffffffu,csum,off);
    }
    clo = csum;
    __syncwarp();

    unsigned prefix = 0;
    if (!ovf && clo <= 256 && 256 < clo + ctot) {
        int k = 256 - clo;       // rank among candidates
        int myc = (cnt < LCAP) ? cnt : LCAP;
        for(int shift=24; shift>=0; shift-=8){
            for(int i=lane;i<256;i+=32) hw[i]=0;
            __syncwarp();
            unsigned hm = (shift==24)? 0u : (0xFFFFFFFFu << (shift+8));
            for(int i=0;i<myc;i++){
                unsigned key = lseg[i];
                if ((key & hm) == (prefix & hm))
                    atomicAdd(&hw[(key>>shift)&255], 1u);
            }
            __syncwarp();
            int d = resolve256(hw, lane, k);
            prefix |= (unsigned)d << shift;
            __syncwarp();
        }
    } else {
        // fallback: full-row 4-pass radix (distribution-independent)
        int k = 256;
        for(int shift=24; shift>=0; shift-=8){
            for(int i=lane;i<256;i+=32) hw[i]=0;
            __syncwarp();
            unsigned hm = (shift==24)? 0u : (0xFFFFFFFFu << (shift+8));
            for(int i=lane;i<SK_;i+=32){
                unsigned key = f2key(src[i]);
                if ((key & hm) == (prefix & hm))
                    atomicAdd(&hw[(key>>shift)&255], 1u);
            }
            __syncwarp();
            int d = resolve256(hw, lane, k);
            prefix |= (unsigned)d << shift;
            __syncwarp();
        }
    }
    if(lane==0) g_stats[row_id] = make_float4(key2f(prefix), m, 0.f, 0.f);
}

// ---------------------------------------------------------------------------
// ctx = softmax(P) @ V, single-pass tf32. 128 q-rows per block; 3 CTAs/SM.
// den computed in-kernel and applied in the epilogue.
// ---------------------------------------------------------------------------
__global__ __launch_bounds__(256, 3) void pv_k(const int* __restrict__ amask)
{
    extern __shared__ unsigned shu[];
    unsigned* Ps = shu;                       // [128][68]
    unsigned* Vs = shu + 128*68;              // [64][72]
    float* thr_s = (float*)(Vs + 64*72);      // 128
    float* max_s = thr_s + 128;
    float* den_s = max_s + 128;               // 128
    unsigned* bs = (unsigned*)(den_s + 128);  // 80 words
    const int z = blockIdx.y, m0 = blockIdx.x*128;
    const int b = z>>4, h = z&15;
    const int t = threadIdx.x, w=t>>5, lane=t&31, g=lane>>2, tig=lane&3;
    const int wm = w>>1, wn = w&1;
    const float* P = g_scores + ((size_t)(z*S_) + m0)*SK_;
    const float* V = g_v + (size_t)z*SK_*64;
    const int* am = amask + b*S_;
    const int pc = (t&15)*4;
    const int pr0 = t>>4;

    if (t < 128) {
        float4 st = g_stats[(size_t)z*S_ + m0 + t];
        thr_s[t]=st.x; max_s[t]=st.y; den_s[t]=0.f;
    } else if (t < 128+80) {
        int wd = t - 128;
        unsigned wb;
        if (wd < 16) wb = 0xFFFFFFFFu;                      // keys 0..511 (past)
        else {
            int s0 = (wd-16)*32;
            wb = 0;
            for (int j = 0; j < 32; j++) wb |= (am[s0+j] != 0 ? (1u<<j) : 0u);
        }
        bs[wd] = wb;
    }
    float acc[2][4][4];
    #pragma unroll
    for(int i=0;i<2;i++)
        #pragma unroll
        for(int j=0;j<4;j++)
            #pragma unroll
            for(int c=0;c<4;c++) acc[i][j][c]=0.f;
    float denp[8];
    #pragma unroll
    for(int i=0;i<8;i++) denp[i]=0.f;
    __syncthreads();

    for(int kc=0;kc<40;kc++){
        const int k0 = kc*64;
        __syncthreads();
        int kg0 = k0 + pc;
        unsigned mw = bs[kg0>>5] >> (kg0&31);
        #pragma unroll
        for(int i=0;i<4;i++){            // V chunk [k][n] stride 72
            int idx = t + i*256, r = idx>>4, c = (idx&15)*4;
            float4 v = *(const float4*)(V + (size_t)(k0+r)*64 + c);
            uint4 u = {f2tf(v.x),f2tf(v.y),f2tf(v.z),f2tf(v.w)};
            *(uint4*)&Vs[r*72 + c] = u;
        }
        #pragma unroll
        for(int i=0;i<8;i++){            // P chunk with exp transform + den
            int r = pr0 + i*16;
            float4 x = *(const float4*)(P + (size_t)r*SK_ + k0 + pc);
            float thr = thr_s[r], mm = max_s[r];
            float p0 = ((mw&1u) && x.x>=thr) ? __expf(x.x-mm) : 0.f;
            float p1 = ((mw&2u) && x.y>=thr) ? __expf(x.y-mm) : 0.f;
            float p2 = ((mw&4u) && x.z>=thr) ? __expf(x.z-mm) : 0.f;
            float p3 = ((mw&8u) && x.w>=thr) ? __expf(x.w-mm) : 0.f;
            denp[i] += (p0+p1)+(p2+p3);
            uint4 u = {f2tf(p0),f2tf(p1),f2tf(p2),f2tf(p3)};
            *(uint4*)&Ps[r*68 + pc] = u;
        }
        __syncthreads();
        #pragma unroll
        for(int kk=0;kk<8;kk++){
            unsigned af[2][4], bf[4][2];
            #pragma unroll
            for(int mi=0;mi<2;mi++){
                const unsigned* p = &Ps[(wm*32+mi*16+g)*68 + kk*8 + tig];
                af[mi][0]=p[0]; af[mi][1]=p[8*68]; af[mi][2]=p[4]; af[mi][3]=p[8*68+4];
            }
            #pragma unroll
            for(int nj=0;nj<4;nj++){
                const unsigned* p = &Vs[(kk*8+tig)*72 + wn*32+nj*8+g];
                bf[nj][0]=p[0]; bf[nj][1]=p[4*72];
            }
            #pragma unroll
            for(int mi=0;mi<2;mi++)
                #pragma unroll
                for(int nj=0;nj<4;nj++) mma8(acc[mi][nj], af[mi], bf[nj]);
        }
    }

    __syncthreads();
    #pragma unroll
    for(int i=0;i<8;i++) atomicAdd(&den_s[pr0 + i*16], denp[i]);
    __syncthreads();

    #pragma unroll
    for(int mi=0;mi<2;mi++){
        int lr = wm*32+mi*16+g;
        int r0 = m0 + lr;
        float inv0 = 1.0f/den_s[lr];
        float inv1 = 1.0f/den_s[lr+8];
        #pragma unroll
        for(int nj=0;nj<4;nj++){
            int c0 = wn*32+nj*8+2*tig;
            float2 v0 = {acc[mi][nj][0]*inv0, acc[mi][nj][1]*inv0};
            float2 v1 = {acc[mi][nj][2]*inv1, acc[mi][nj][3]*inv1};
            *(float2*)(g_ctx + ((size_t)(b*S_ + r0))*1024 + h*64 + c0)   = v0;
            *(float2*)(g_ctx + ((size_t)(b*S_ + r0+8))*1024 + h*64 + c0) = v1;
        }
    }
}

// ---------------------------------------------------------------------------
extern "C" void kernel_launch(void* const* d_in, const int* in_sizes, int n_in,
                              void* d_out, int out_size)
{
    const float* hs     = (const float*)d_in[0];
    const int*   amask  = (const int*)  d_in[1];
    const float* past_k = (const float*)d_in[2];
    const float* past_v = (const float*)d_in[3];
    const float* Wq = (const float*)d_in[4];
    const float* bq = (const float*)d_in[5];
    const float* Wk = (const float*)d_in[6];
    const float* bk = (const float*)d_in[7];
    const float* Wv = (const float*)d_in[8];
    const float* bv = (const float*)d_in[9];
    const float* Wo = (const float*)d_in[10];
    const float* bo = (const float*)d_in[11];
    float* out = (float*)d_out;

    const int sc_smem = 2*128*68*4;                          // 69,632
    const int th_smem = 8*CAP_*4 + 8*264*4 + 64*4;           // 45,568
    const int pv_smem = (128*68 + 64*72 + 3*128)*4 + 80*4;   // 55,104
    cudaFuncSetAttribute(scores_k, cudaFuncAttributeMaxDynamicSharedMemorySize, sc_smem);
    cudaFuncSetAttribute(thresh_k, cudaFuncAttributeMaxDynamicSharedMemorySize, th_smem);
    cudaFuncSetAttribute(pv_k,     cudaFuncAttributeMaxDynamicSharedMemorySize, pv_smem);

    // Launch order keeps thresh_k in the ncu capture slot (4th launch).
    gemm4k<<<dim3(8,32,3), 256>>>(hs, Wq, bq, Wk, bk, Wv, bv, nullptr, 4); // QKV proj
    copy_past_kernel<<<1024, 256>>>(past_k, past_v);
    scores_k<<<dim3(20, 16, 32), 256, sc_smem>>>();
    thresh_k<<<NROW/8, 256, th_smem>>>(amask);
    pv_k<<<dim3(16, 32), 256, pv_smem>>>(amask);
    gemm4k<<<dim3(8,32), 256>>>(nullptr, Wo, bo, nullptr, nullptr, nullptr, nullptr, out, 3);

    float* nk = out + (size_t)B_ * S_ * D_;
    float* nv = nk + (size_t)BH_ * MEM_ * HD_;
    copy_new_kernel<<<1024, 256>>>(nk, nv);
}

// round 17
// speedup vs baseline: 1.3994x; 1.3994x over previous
#include <cuda_runtime.h>

#define B_   2
#define S_   2048
#define D_   1024
#define H_   16
#define HD_  64
#define MEM_ 512
#define SK_  2560
#define BH_  32
#define NROW (BH_*S_)   // 65536
#define CAP_ 1152       // per-warp candidate buffer (bracket holds ~660)

// Scratch (static device allocs only)
__device__ float  g_q[BH_*S_*HD_];
__device__ float  g_k[BH_*SK_*HD_];
__device__ float  g_v[BH_*SK_*HD_];
__device__ float  g_ctx[B_*S_*D_];
__device__ float  g_scores[(size_t)NROW*SK_];   // 671 MB
__device__ float4 g_stats[NROW];                // thr, max, -, -

__device__ __forceinline__ unsigned f2tf(float f){
    unsigned r; asm("cvt.rna.tf32.f32 %0, %1;" : "=r"(r) : "f"(f)); return r;
}
__device__ __forceinline__ void tfsplit(float x, unsigned& h, unsigned& l){
    h = f2tf(x);
    l = f2tf(x - __uint_as_float(h));
}
__device__ __forceinline__ void mma8(float* c, const unsigned* a, const unsigned* b){
    asm volatile("mma.sync.aligned.m16n8k8.row.col.f32.tf32.tf32.f32 "
      "{%0,%1,%2,%3}, {%4,%5,%6,%7}, {%8,%9}, {%0,%1,%2,%3};\n"
      : "+f"(c[0]), "+f"(c[1]), "+f"(c[2]), "+f"(c[3])
      : "r"(a[0]),"r"(a[1]),"r"(a[2]),"r"(a[3]), "r"(b[0]),"r"(b[1]));
}
__device__ __forceinline__ void mma8x3(float* c, const unsigned* ah, const unsigned* al,
                                       const unsigned* bh, const unsigned* bl){
    mma8(c, al, bh);
    mma8(c, ah, bl);
    mma8(c, ah, bh);
}

// ---------------------------------------------------------------------------
// Dense GEMM (3xTF32): C(4096x1024) = A(4096x1024)@W(1024x1024)+bias.
// mode 0/1/2: head-split epilogue; mode 3: row-major dst; mode 4: fused QK.
// ---------------------------------------------------------------------------
__global__ __launch_bounds__(256, 2) void gemm4k(
    const float* __restrict__ A, const float* __restrict__ W,
    const float* __restrict__ bias, const float* __restrict__ W2,
    const float* __restrict__ bias2, float* __restrict__ dst, int mode)
{
    __shared__ unsigned Ah[2][128*20], Al[2][128*20];
    __shared__ unsigned Bh[2][16*136], Bl[2][16*136];
    int em = mode;
    const float* Wp = W;
    const float* bp = bias;
    if (mode == 4) {
        em = (blockIdx.z == 0) ? 0 : 1;
        if (blockIdx.z == 1) { Wp = W2; bp = bias2; }
    }
    const float* Ap = (em==3) ? g_ctx : A;
    const int t = threadIdx.x;
    const int m0 = blockIdx.y*128, n0 = blockIdx.x*128;
    const int w = t>>5, lane = t&31, g = lane>>2, tig = lane&3;
    const int wm = w>>2, wn = w&3;

    const int am_r = t>>2;
    const int am_k = (t&3)*4;
    const int bm_k = t>>5;
    const int bm_n = (t&31)*4;

    const float* Arow0 = Ap + (size_t)(m0+am_r)*1024 + am_k;
    const float* Arow1 = Arow0 + (size_t)64*1024;
    const float* Wrow0 = Wp + (size_t)bm_k*1024 + n0 + bm_n;
    const float* Wrow1 = Wrow0 + (size_t)8*1024;

    float acc[4][4][4];
    #pragma unroll
    for(int i=0;i<4;i++)
        #pragma unroll
        for(int j=0;j<4;j++)
            #pragma unroll
            for(int c=0;c<4;c++) acc[i][j][c]=0.f;

    float4 la0,la1,lb0,lb1;
    auto ldg = [&](int kt){
        la0 = *(const float4*)(Arow0 + kt*16);
        la1 = *(const float4*)(Arow1 + kt*16);
        lb0 = *(const float4*)(Wrow0 + (size_t)kt*16*1024);
        lb1 = *(const float4*)(Wrow1 + (size_t)kt*16*1024);
    };
    auto sts = [&](int buf){
        uint4 uh, ul;
        tfsplit(la0.x,uh.x,ul.x); tfsplit(la0.y,uh.y,ul.y);
        tfsplit(la0.z,uh.z,ul.z); tfsplit(la0.w,uh.w,ul.w);
        *(uint4*)&Ah[buf][am_r*20 + am_k] = uh;
        *(uint4*)&Al[buf][am_r*20 + am_k] = ul;
        tfsplit(la1.x,uh.x,ul.x); tfsplit(la1.y,uh.y,ul.y);
        tfsplit(la1.z,uh.z,ul.z); tfsplit(la1.w,uh.w,ul.w);
        *(uint4*)&Ah[buf][(am_r+64)*20 + am_k] = uh;
        *(uint4*)&Al[buf][(am_r+64)*20 + am_k] = ul;
        tfsplit(lb0.x,uh.x,ul.x); tfsplit(lb0.y,uh.y,ul.y);
        tfsplit(lb0.z,uh.z,ul.z); tfsplit(lb0.w,uh.w,ul.w);
        *(uint4*)&Bh[buf][bm_k*136 + bm_n] = uh;
        *(uint4*)&Bl[buf][bm_k*136 + bm_n] = ul;
        tfsplit(lb1.x,uh.x,ul.x); tfsplit(lb1.y,uh.y,ul.y);
        tfsplit(lb1.z,uh.z,ul.z); tfsplit(lb1.w,uh.w,ul.w);
        *(uint4*)&Bh[buf][(bm_k+8)*136 + bm_n] = uh;
        *(uint4*)&Bl[buf][(bm_k+8)*136 + bm_n] = ul;
    };
    auto compute = [&](int buf){
        #pragma unroll
        for(int kk=0;kk<2;kk++){
            unsigned ah[4][4], al[4][4], bh[4][2], bl[4][2];
            #pragma unroll
            for(int mi=0;mi<4;mi++){
                int base = (wm*64+mi*16+g)*20 + kk*8 + tig;
                ah[mi][0]=Ah[buf][base];       al[mi][0]=Al[buf][base];
                ah[mi][1]=Ah[buf][base+8*20];  al[mi][1]=Al[buf][base+8*20];
                ah[mi][2]=Ah[buf][base+4];     al[mi][2]=Al[buf][base+4];
                ah[mi][3]=Ah[buf][base+8*20+4];al[mi][3]=Al[buf][base+8*20+4];
            }
            #pragma unroll
            for(int nj=0;nj<4;nj++){
                int base = (kk*8+tig)*136 + wn*32+nj*8+g;
                bh[nj][0]=Bh[buf][base];        bl[nj][0]=Bl[buf][base];
                bh[nj][1]=Bh[buf][base+4*136];  bl[nj][1]=Bl[buf][base+4*136];
            }
            #pragma unroll
            for(int mi=0;mi<4;mi++)
                #pragma unroll
                for(int nj=0;nj<4;nj++)
                    mma8x3(acc[mi][nj], ah[mi], al[mi], bh[nj], bl[nj]);
        }
    };

    ldg(0); sts(0); __syncthreads();
    for(int kt=0;kt<64;kt++){
        if(kt<63) ldg(kt+1);
        compute(kt&1);
        if(kt<63){ sts((kt+1)&1); __syncthreads(); }
    }

    const int b = m0>>11;
    #pragma unroll
    for(int nj=0;nj<4;nj++){
        int c0 = n0 + wn*32 + nj*8 + 2*tig;
        float bv0 = bp[c0], bv1 = bp[c0+1];
        int h = c0>>6, hd = c0&63;
        #pragma unroll
        for(int mi=0;mi<4;mi++){
            int r0 = m0 + wm*64 + mi*16 + g;
            int s0 = r0 & 2047;
            float2 v0 = {acc[mi][nj][0]+bv0, acc[mi][nj][1]+bv1};
            float2 v1 = {acc[mi][nj][2]+bv0, acc[mi][nj][3]+bv1};
            if(em==3){
                *(float2*)(dst + (size_t)r0*1024 + c0)     = v0;
                *(float2*)(dst + (size_t)(r0+8)*1024 + c0) = v1;
            } else {
                float* base = (em==0)? g_q : (em==1? g_k : g_v);
                size_t roff = (em==0)? ((size_t)(b*16+h)*S_)
                                     : ((size_t)(b*16+h)*SK_ + MEM_);
                *(float2*)(base + (roff + s0)*64 + hd)     = v0;
                *(float2*)(base + (roff + s0 + 8)*64 + hd) = v1;
            }
        }
    }
}

__global__ void copy_past_kernel(const float* __restrict__ pk,
                                 const float* __restrict__ pv)
{
    int i = blockIdx.x * blockDim.x + threadIdx.x;
    if (i < BH_ * MEM_ * HD_ / 4) {
        int e = i * 4;
        int bh = e >> 15, rem = e & 32767;
        *(float4*)(g_k + (size_t)bh*(SK_*HD_) + rem) = *(const float4*)(pk + e);
        *(float4*)(g_v + (size_t)bh*(SK_*HD_) + rem) = *(const float4*)(pv + e);
    }
}
__global__ void copy_new_kernel(float* __restrict__ nk, float* __restrict__ nv)
{
    int i = blockIdx.x * blockDim.x + threadIdx.x;
    if (i < BH_ * MEM_ * HD_ / 4) {
        int e = i * 4;
        int bh = e >> 15, rem = e & 32767;
        size_t src = (size_t)bh*(SK_*HD_) + S_*HD_ + rem;
        *(float4*)(nk + e) = *(const float4*)(g_k + src);
        *(float4*)(nv + e) = *(const float4*)(g_v + src);
    }
}

// ---------------------------------------------------------------------------
// scores = (Q*0.125) K^T -> g_scores. Single-pass tf32, scale folded into Q.
// ---------------------------------------------------------------------------
__global__ __launch_bounds__(256, 2) void scores_k()
{
    extern __shared__ unsigned shsc[];
    unsigned* Qs = shsc;               // [128][68] tf32 bits (pre-scaled)
    unsigned* Ks = shsc + 128*68;      // [128][68]
    const int z = blockIdx.z;
    const int m0 = blockIdx.y*128, n0 = blockIdx.x*128;
    const int t = threadIdx.x, w = t>>5, lane=t&31, g=lane>>2, tig=lane&3;
    const int wm = w>>2, wn = w&3;
    const float* Q = g_q + ((size_t)z*S_ + m0)*64;
    const float* K = g_k + ((size_t)z*SK_ + n0)*64;

    #pragma unroll
    for(int i=0;i<8;i++){
        int idx = t + i*256, r = idx>>4, c = (idx&15)*4;
        float4 a = *(const float4*)(Q + (size_t)r*64 + c);
        uint4 ua = {f2tf(a.x*0.125f),f2tf(a.y*0.125f),
                    f2tf(a.z*0.125f),f2tf(a.w*0.125f)};
        *(uint4*)&Qs[r*68+c] = ua;
        float4 bb = *(const float4*)(K + (size_t)r*64 + c);
        uint4 ub = {f2tf(bb.x),f2tf(bb.y),f2tf(bb.z),f2tf(bb.w)};
        *(uint4*)&Ks[r*68+c] = ub;
    }
    __syncthreads();

    float acc[4][4][4] = {};
    #pragma unroll
    for(int kk=0;kk<8;kk++){
        unsigned af[4][4], bf[4][2];
        #pragma unroll
        for(int mi=0;mi<4;mi++){
            const unsigned* p = &Qs[(wm*64+mi*16+g)*68 + kk*8 + tig];
            af[mi][0]=p[0]; af[mi][1]=p[8*68]; af[mi][2]=p[4]; af[mi][3]=p[8*68+4];
        }
        #pragma unroll
        for(int nj=0;nj<4;nj++){
            const unsigned* p = &Ks[(wn*32+nj*8+g)*68 + kk*8 + tig];
            bf[nj][0]=p[0]; bf[nj][1]=p[4];
        }
        #pragma unroll
        for(int mi=0;mi<4;mi++)
            #pragma unroll
            for(int nj=0;nj<4;nj++) mma8(acc[mi][nj], af[mi], bf[nj]);
    }

    float* out = g_scores + ((size_t)(z*S_ + m0))*SK_ + n0;
    #pragma unroll
    for(int mi=0;mi<4;mi++){
        int r0 = wm*64+mi*16+g;
        #pragma unroll
        for(int nj=0;nj<4;nj++){
            int c0 = wn*32+nj*8+2*tig;
            float2 v0 = {acc[mi][nj][0], acc[mi][nj][1]};
            float2 v1 = {acc[mi][nj][2], acc[mi][nj][3]};
            *(float2*)(out + (size_t)r0*SK_ + c0)     = v0;
            *(float2*)(out + (size_t)(r0+8)*SK_ + c0) = v1;
        }
    }
}

// ---------------------------------------------------------------------------
// Radix helpers
// ---------------------------------------------------------------------------
__device__ __forceinline__ unsigned f2key(float f) {
    unsigned u = __float_as_uint(f);
    return u ^ (unsigned(int(u) >> 31) | 0x80000000u);   // SHF + LOP3
}
__device__ __forceinline__ float key2f(unsigned k) {
    unsigned u = (k & 0x80000000u) ? (k ^ 0x80000000u) : ~k;
    return __uint_as_float(u);
}
__device__ __forceinline__ int resolve256(const unsigned* hist, int lane, int& k){
    unsigned cnt[8], local = 0;
    #pragma unroll
    for (int j = 0; j < 8; j++) { cnt[j] = hist[lane*8+j]; local += cnt[j]; }
    unsigned x = local;
    #pragma unroll
    for (int off = 1; off < 32; off <<= 1) {
        unsigned y = __shfl_up_sync(0xffffffffu, x, off);
        if (lane >= off) x += y;
    }
    unsigned incl = x, excl = x - local;
    bool flag = ((unsigned)k >= excl) && ((unsigned)k < incl);
    unsigned bal = __ballot_sync(0xffffffffu, flag);
    int src = __ffs(bal) - 1;
    int digit = 0, newk = 0;
    if (lane == src) {
        unsigned c = excl; int j = 0;
        for (; j < 8; j++) { if (c + cnt[j] > (unsigned)k) break; c += cnt[j]; }
        digit = lane*8 + j;
        newk  = k - (int)c;
    }
    digit = __shfl_sync(0xffffffffu, digit, src);
    k     = __shfl_sync(0xffffffffu, newk,  src);
    return digit;
}

// ---------------------------------------------------------------------------
// thresh_k v4b: warp per row; emits (thr, masked max) — den lives in pv_k.
// Pass 1: moments + max (all-ones-mask fast path skips bitset probes).
// Pass 2: bracket [mu-2.1s, mu-0.6s): count-below + ballot-gather candidates.
// Exact rank-(256-c_lo) radix over ~660 candidates; full-row radix fallback.
// ---------------------------------------------------------------------------
__global__ __launch_bounds__(256) void thresh_k(const int* __restrict__ amask)
{
    extern __shared__ unsigned tsm[];
    unsigned* cand = tsm;                        // 8*CAP_
    unsigned* hist = cand + 8*CAP_;              // 8*264
    unsigned* mbits= hist + 8*264;               // 64 words
    __shared__ int s_allones;
    const int t = threadIdx.x, w = t>>5, lane = t&31;
    const int row_id = blockIdx.x*8 + w;
    const int bh = row_id >> 11;
    const int b = bh >> 4;
    const float* src = g_scores + (size_t)row_id*SK_;
    const int* am = amask + b*S_;
    unsigned* cw = cand + w*CAP_;
    unsigned* hw = hist + w*264;

    if (t == 0) s_allones = 1;
    __syncthreads();
    if (t < 64) {
        unsigned wb = 0;
        for (int j = 0; j < 32; j++) wb |= (am[t*32+j] != 0 ? (1u<<j) : 0u);
        mbits[t] = wb;
        if (wb != 0xFFFFFFFFu) s_allones = 0;
    }
    __syncthreads();
    const bool allones = (s_allones != 0);
    auto masked = [&](int kg)->bool {
        if (kg < MEM_) return true;
        int s = kg - MEM_;
        return (mbits[s>>5] >> (s&31)) & 1u;
    };

    // ---- Pass 1: moments over all elements + masked max ------------------
    float s1 = 0.f, s2 = 0.f, m = -1e30f;
    if (allones) {
        for(int it=0; it<10; it++){
            float4 va = *(const float4*)(src + (it*64 + lane)*4);
            float4 vb = *(const float4*)(src + (it*64 + 32 + lane)*4);
            #pragma unroll
            for(int j=0;j<4;j++){
                float x = (&va.x)[j]; s1 += x; s2 += x*x; m = fmaxf(m, x);
            }
            #pragma unroll
            for(int j=0;j<4;j++){
                float x = (&vb.x)[j]; s1 += x; s2 += x*x; m = fmaxf(m, x);
            }
        }
    } else {
        for(int it=0; it<10; it++){
            int ia = (it*64 + lane)*4;
            int ib = (it*64 + 32 + lane)*4;
            float4 va = *(const float4*)(src + ia);
            float4 vb = *(const float4*)(src + ib);
            #pragma unroll
            for(int j=0;j<4;j++){
                float x = (&va.x)[j]; s1 += x; s2 += x*x;
                if (masked(ia+j)) m = fmaxf(m, x);
            }
            #pragma unroll
            for(int j=0;j<4;j++){
                float x = (&vb.x)[j]; s1 += x; s2 += x*x;
                if (masked(ib+j)) m = fmaxf(m, x);
            }
        }
    }
    #pragma unroll
    for(int off=16;off;off>>=1){
        s1 += __shfl_xor_sync(0xffffffffu,s1,off);
        s2 += __shfl_xor_sync(0xffffffffu,s2,off);
        m = fmaxf(m, __shfl_xor_sync(0xffffffffu,m,off));
    }
    const float inv_n = 1.0f/2560.f;
    float mu  = s1*inv_n;
    float var = fmaxf(s2*inv_n - mu*mu, 0.f);
    float sg  = sqrtf(var);
    float lo  = mu - 2.1f*sg;    // bracket for rank-256 (z~-1.28)
    float hi  = mu - 0.6f*sg;

    // ---- Pass 2: count < lo, gather [lo, hi) -----------------------------
    if(lane==0) hw[256]=0;
    __syncwarp();
    int clo = 0;
    for(int it=0; it<10; it++){
        int ia = (it*64 + lane)*4;
        int ib = (it*64 + 32 + lane)*4;
        float4 va = *(const float4*)(src + ia);
        float4 vb = *(const float4*)(src + ib);
        #pragma unroll
        for(int half=0; half<2; half++){
            const float4& v = half ? vb : va;
            #pragma unroll
            for(int j=0;j<4;j++){
                float x = (&v.x)[j];
                bool blo = x < lo;
                bool bin = (!blo) && (x < hi);
                clo += blo;
                unsigned pm = __ballot_sync(0xffffffffu, bin);
                if (bin){
                    int rk = __popc(pm & ((1u<<lane)-1u));
                    int ldr = __ffs(pm)-1;
                    unsigned base = 0;
                    if (lane == ldr) base = atomicAdd(&hw[256], (unsigned)__popc(pm));
                    base = __shfl_sync(pm, base, ldr);
                    unsigned p = base + rk;
                    if (p < CAP_) cw[p] = f2key(x);
                }
            }
        }
    }
    #pragma unroll
    for(int off=16;off;off>>=1) clo += __shfl_xor_sync(0xffffffffu,clo,off);
    __syncwarp();
    int c = hw[256];

    unsigned prefix = 0;
    if (c <= CAP_ && clo <= 256 && 256 < clo + c) {
        int k = 256 - clo;       // rank among candidates
        for(int shift=24; shift>=0; shift-=8){
            for(int i=lane;i<256;i+=32) hw[i]=0;
            __syncwarp();
            unsigned hm = (shift==24)? 0u : (0xFFFFFFFFu << (shift+8));
            for(int i=lane;i<c;i+=32){
                unsigned key = cw[i];
                if ((key & hm) == (prefix & hm))
                    atomicAdd(&hw[(key>>shift)&255], 1u);
            }
            __syncwarp();
            int d = resolve256(hw, lane, k);
            prefix |= (unsigned)d << shift;
            __syncwarp();
        }
    } else {
        // fallback: full-row 4-pass radix (distribution-independent)
        int k = 256;
        for(int shift=24; shift>=0; shift-=8){
            for(int i=lane;i<256;i+=32) hw[i]=0;
            __syncwarp();
            unsigned hm = (shift==24)? 0u : (0xFFFFFFFFu << (shift+8));
            for(int i=lane;i<SK_;i+=32){
                unsigned key = f2key(src[i]);
                if ((key & hm) == (prefix & hm))
                    atomicAdd(&hw[(key>>shift)&255], 1u);
            }
            __syncwarp();
            int d = resolve256(hw, lane, k);
            prefix |= (unsigned)d << shift;
            __syncwarp();
        }
    }
    if(lane==0) g_stats[row_id] = make_float4(key2f(prefix), m, 0.f, 0.f);
}

// ---------------------------------------------------------------------------
// ctx = softmax(P) @ V, single-pass tf32. 128 q-rows per block; 3 CTAs/SM.
// den computed in-kernel (16 threads/row partials -> smem reduce); epilogue
// applies 1/den (normalization is linear in the PV product).
// ---------------------------------------------------------------------------
__global__ __launch_bounds__(256, 3) void pv_k(const int* __restrict__ amask)
{
    extern __shared__ unsigned shu[];
    unsigned* Ps = shu;                       // [128][68]
    unsigned* Vs = shu + 128*68;              // [64][72]
    float* thr_s = (float*)(Vs + 64*72);      // 128
    float* max_s = thr_s + 128;
    float* den_s = max_s + 128;               // 128
    unsigned* bs = (unsigned*)(den_s + 128);  // 80 words: bit i = key i allowed
    const int z = blockIdx.y, m0 = blockIdx.x*128;
    const int b = z>>4, h = z&15;
    const int t = threadIdx.x, w=t>>5, lane=t&31, g=lane>>2, tig=lane&3;
    const int wm = w>>1, wn = w&1;
    const float* P = g_scores + ((size_t)(z*S_) + m0)*SK_;
    const float* V = g_v + (size_t)z*SK_*64;
    const int* am = amask + b*S_;
    const int pc = (t&15)*4;
    const int pr0 = t>>4;

    if (t < 128) {
        float4 st = g_stats[(size_t)z*S_ + m0 + t];
        thr_s[t]=st.x; max_s[t]=st.y; den_s[t]=0.f;
    } else if (t < 128+80) {
        int wd = t - 128;
        unsigned wb;
        if (wd < 16) wb = 0xFFFFFFFFu;                      // keys 0..511 (past)
        else {
            int s0 = (wd-16)*32;
            wb = 0;
            for (int j = 0; j < 32; j++) wb |= (am[s0+j] != 0 ? (1u<<j) : 0u);
        }
        bs[wd] = wb;
    }
    float acc[2][4][4];
    #pragma unroll
    for(int i=0;i<2;i++)
        #pragma unroll
        for(int j=0;j<4;j++)
            #pragma unroll
            for(int c=0;c<4;c++) acc[i][j][c]=0.f;
    float denp[8];
    #pragma unroll
    for(int i=0;i<8;i++) denp[i]=0.f;
    __syncthreads();

    for(int kc=0;kc<40;kc++){
        const int k0 = kc*64;
        __syncthreads();
        int kg0 = k0 + pc;
        unsigned mw = bs[kg0>>5] >> (kg0&31);
        #pragma unroll
        for(int i=0;i<4;i++){            // V chunk [k][n] stride 72
            int idx = t + i*256, r = idx>>4, c = (idx&15)*4;
            float4 v = *(const float4*)(V + (size_t)(k0+r)*64 + c);
            uint4 u = {f2tf(v.x),f2tf(v.y),f2tf(v.z),f2tf(v.w)};
            *(uint4*)&Vs[r*72 + c] = u;
        }
        #pragma unroll
        for(int i=0;i<8;i++){            // P chunk with exp transform + den
            int r = pr0 + i*16;
            float4 x = *(const float4*)(P + (size_t)r*SK_ + k0 + pc);
            float thr = thr_s[r], mm = max_s[r];
            float p0 = ((mw&1u) && x.x>=thr) ? __expf(x.x-mm) : 0.f;
            float p1 = ((mw&2u) && x.y>=thr) ? __expf(x.y-mm) : 0.f;
            float p2 = ((mw&4u) && x.z>=thr) ? __expf(x.z-mm) : 0.f;
            float p3 = ((mw&8u) && x.w>=thr) ? __expf(x.w-mm) : 0.f;
            denp[i] += (p0+p1)+(p2+p3);
            uint4 u = {f2tf(p0),f2tf(p1),f2tf(p2),f2tf(p3)};
            *(uint4*)&Ps[r*68 + pc] = u;
        }
        __syncthreads();
        #pragma unroll
        for(int kk=0;kk<8;kk++){
            unsigned af[2][4], bf[4][2];
            #pragma unroll
            for(int mi=0;mi<2;mi++){
                const unsigned* p = &Ps[(wm*32+mi*16+g)*68 + kk*8 + tig];
                af[mi][0]=p[0]; af[mi][1]=p[8*68]; af[mi][2]=p[4]; af[mi][3]=p[8*68+4];
            }
            #pragma unroll
            for(int nj=0;nj<4;nj++){
                const unsigned* p = &Vs[(kk*8+tig)*72 + wn*32+nj*8+g];
                bf[nj][0]=p[0]; bf[nj][1]=p[4*72];
            }
            #pragma unroll
            for(int mi=0;mi<2;mi++)
                #pragma unroll
                for(int nj=0;nj<4;nj++) mma8(acc[mi][nj], af[mi], bf[nj]);
        }
    }

    // reduce den partials (16 threads per row)
    __syncthreads();
    #pragma unroll
    for(int i=0;i<8;i++) atomicAdd(&den_s[pr0 + i*16], denp[i]);
    __syncthreads();

    #pragma unroll
    for(int mi=0;mi<2;mi++){
        int lr = wm*32+mi*16+g;
        int r0 = m0 + lr;
        float inv0 = 1.0f/den_s[lr];
        float inv1 = 1.0f/den_s[lr+8];
        #pragma unroll
        for(int nj=0;nj<4;nj++){
            int c0 = wn*32+nj*8+2*tig;
            float2 v0 = {acc[mi][nj][0]*inv0, acc[mi][nj][1]*inv0};
            float2 v1 = {acc[mi][nj][2]*inv1, acc[mi][nj][3]*inv1};
            *(float2*)(g_ctx + ((size_t)(b*S_ + r0))*1024 + h*64 + c0)   = v0;
            *(float2*)(g_ctx + ((size_t)(b*S_ + r0+8))*1024 + h*64 + c0) = v1;
        }
    }
}

// ---------------------------------------------------------------------------
extern "C" void kernel_launch(void* const* d_in, const int* in_sizes, int n_in,
                              void* d_out, int out_size)
{
    const float* hs     = (const float*)d_in[0];
    const int*   amask  = (const int*)  d_in[1];
    const float* past_k = (const float*)d_in[2];
    const float* past_v = (const float*)d_in[3];
    const float* Wq = (const float*)d_in[4];
    const float* bq = (const float*)d_in[5];
    const float* Wk = (const float*)d_in[6];
    const float* bk = (const float*)d_in[7];
    const float* Wv = (const float*)d_in[8];
    const float* bv = (const float*)d_in[9];
    const float* Wo = (const float*)d_in[10];
    const float* bo = (const float*)d_in[11];
    float* out = (float*)d_out;

    const int sc_smem = 2*128*68*4;                          // 69,632
    const int th_smem = 8*CAP_*4 + 8*264*4 + 64*4;           // 45,568
    const int pv_smem = (128*68 + 64*72 + 3*128)*4 + 80*4;   // 55,104
    cudaFuncSetAttribute(scores_k, cudaFuncAttributeMaxDynamicSharedMemorySize, sc_smem);
    cudaFuncSetAttribute(thresh_k, cudaFuncAttributeMaxDynamicSharedMemorySize, th_smem);
    cudaFuncSetAttribute(pv_k,     cudaFuncAttributeMaxDynamicSharedMemorySize, pv_smem);

    // Launch order keeps thresh_k in the ncu capture slot (4th launch).
    gemm4k<<<dim3(8,32,2), 256>>>(hs, Wq, bq, Wk, bk, nullptr, 4);   // fused Q+K proj
    copy_past_kernel<<<1024, 256>>>(past_k, past_v);
    scores_k<<<dim3(20, 16, 32), 256, sc_smem>>>();
    thresh_k<<<NROW/8, 256, th_smem>>>(amask);
    gemm4k<<<dim3(8,32), 256>>>(hs, Wv, bv, nullptr, nullptr, nullptr, 2);
    pv_k<<<dim3(16, 32), 256, pv_smem>>>(amask);
    gemm4k<<<dim3(8,32), 256>>>(nullptr, Wo, bo, nullptr, nullptr, out, 3);

    float* nk = out + (size_t)B_ * S_ * D_;
    float* nv = nk + (size_t)BH_ * MEM_ * HD_;
    copy_new_kernel<<<1024, 256>>>(nk, nv);
}